// round 8
// baseline (speedup 1.0000x reference)
#include <cuda_runtime.h>
#include <math.h>

// ---------------------------------------------------------------------------
// Shapes: N=16, F=5, V=4 -> 320 images of 3x224x224
// conv1: 3->3, 3x3, s2: 224->111 ; maxpool3/3 -> 37 ; relu
// conv2: 3->1, 3x3, s2: 37->18   ; maxpool3/3 -> 6  ; relu
// flatten 36 -> linear -> feat[320,6]; graph ops + MLP -> [16,6]
//
// K1: conv1+pool+relu, 1712x256, one output/thread (proven DRAM plateau).
// K2: epilogue, 16 blocks x 512 thr — block n owns sample n end-to-end:
//     conv2+pool+linear for its 20 images (feats in smem), then graph ops +
//     readout. NO cross-block communication: no atomics, fences, or spins.
// ---------------------------------------------------------------------------

#define NIMG 320
#define H1_STRIDE (3 * 1369)
#define TOTAL1 (NIMG * 1369)
#define NBLK1 1712

__device__ float g_h1[NIMG * H1_STRIDE];

// ---------------- Kernel 1: conv1 + maxpool3 + relu ------------------------
__global__ __launch_bounds__(256, 3)
void conv1_pool_kernel(const float* __restrict__ nodes,
                       const float* __restrict__ w,   // [3,3,3,3] OIHW
                       const float* __restrict__ b)   // [3]
{
    __shared__ float sw[81];
    __shared__ float sb[3];
    int tid = threadIdx.x;
    if (tid < 81) sw[tid] = w[tid];
    if (tid < 3)  sb[tid] = b[tid];
    __syncthreads();

    int idx = blockIdx.x * 256 + tid;
    if (idx >= TOTAL1) return;
    int px  = idx % 37;
    int rem = idx / 37;
    int py  = rem % 37;
    int img = rem / 37;

    const float* base = nodes + (size_t)img * 150528
                              + (size_t)(6 * py) * 224 + 6 * px;

    float acc[9][3];
#pragma unroll
    for (int p = 0; p < 9; p++) {
        acc[p][0] = sb[0]; acc[p][1] = sb[1]; acc[p][2] = sb[2];
    }

#pragma unroll
    for (int ic = 0; ic < 3; ic++) {
        const float* chan = base + ic * 50176;
        float2 p2[7][4];
#pragma unroll
        for (int r = 0; r < 7; r++) {
            const float* rp = chan + r * 224;
            p2[r][0] = *(const float2*)(rp);
            p2[r][1] = *(const float2*)(rp + 2);
            p2[r][2] = *(const float2*)(rp + 4);
            p2[r][3] = *(const float2*)(rp + 6);
        }
#pragma unroll
        for (int ky = 0; ky < 3; ky++)
#pragma unroll
            for (int kx = 0; kx < 3; kx++) {
                float w0 = sw[ic * 9 + ky * 3 + kx];
                float w1 = sw[27 + ic * 9 + ky * 3 + kx];
                float w2 = sw[54 + ic * 9 + ky * 3 + kx];
#pragma unroll
                for (int cy = 0; cy < 3; cy++)
#pragma unroll
                    for (int cx = 0; cx < 3; cx++) {
                        int col = 2 * cx + kx;
                        float v = (col & 1) ? p2[2 * cy + ky][col >> 1].y
                                            : p2[2 * cy + ky][col >> 1].x;
                        acc[cy * 3 + cx][0] += v * w0;
                        acc[cy * 3 + cx][1] += v * w1;
                        acc[cy * 3 + cx][2] += v * w2;
                    }
            }
    }

#pragma unroll
    for (int oc = 0; oc < 3; oc++) {
        float m = acc[0][oc];
#pragma unroll
        for (int p = 1; p < 9; p++) m = fmaxf(m, acc[p][oc]);
        m = fmaxf(m, 0.0f);
        g_h1[(size_t)img * H1_STRIDE + oc * 1369 + py * 37 + px] = m;
    }
}

// ---------------- Kernel 2: per-sample epilogue (no cross-block sync) ------
__global__ __launch_bounds__(512)
void epilogue_kernel(const float* __restrict__ pos,     // [16,5,4,6]
                     const float* __restrict__ attmap,  // [16,5,4,4]
                     const float* __restrict__ c2w, const float* __restrict__ c2b,
                     const float* __restrict__ lw,  const float* __restrict__ lb,
                     const float* __restrict__ wfc_w, const float* __restrict__ wfc_b,
                     const float* __restrict__ fm_w,  const float* __restrict__ fm_b,
                     const float* __restrict__ lm_w,  const float* __restrict__ lm_b,
                     const float* __restrict__ fc1_w, const float* __restrict__ fc1_b,
                     const float* __restrict__ fc2_w, const float* __restrict__ fc2_b,
                     const float* __restrict__ fc3_w, const float* __restrict__ fc3_b,
                     float* __restrict__ out)           // [16,6]
{
    __shared__ float sw2[27];
    __shared__ float s_conv[20][36][9];   // 25.9 KB
    __shared__ float s_hs[20][36];
    __shared__ float s_feat[20][6];
    __shared__ float r_ps[20][6];
    __shared__ float r_asrc[20];
    __shared__ float r_btgt[20];
    __shared__ float r_pm[20][6];
    __shared__ float r_inp[240];
    __shared__ float r_part[240];
    __shared__ float r_r1[120];
    __shared__ float r_r2[60];

    const int n = blockIdx.x;
    const int t = threadIdx.x;
    if (t < 27) sw2[t] = c2w[t];
    __syncthreads();

    // conv2(s2) for all 20 images of this sample: 6480 items, L2-resident.
    const float bias2 = __ldg(c2b);
    for (int i = t; i < 20 * 324; i += 512) {
        int il   = i / 324;
        int posn = i - il * 324;
        int pool = posn / 9, cp = posn - pool * 9;
        int py = pool / 6, px = pool - py * 6;
        int cy = 3 * py + cp / 3;
        int cx = 3 * px + cp % 3;
        const float* src = g_h1 + (size_t)(n * 20 + il) * H1_STRIDE
                                + (2 * cy) * 37 + 2 * cx;
        float s = bias2;
#pragma unroll
        for (int ic = 0; ic < 3; ic++)
#pragma unroll
            for (int ky = 0; ky < 3; ky++)
#pragma unroll
                for (int kx = 0; kx < 3; kx++)
                    s += __ldg(src + ic * 1369 + ky * 37 + kx)
                         * sw2[ic * 9 + ky * 3 + kx];
        s_conv[il][pool][cp] = s;
    }
    __syncthreads();

    // maxpool over 9 conv positions + relu
    for (int i = t; i < 20 * 36; i += 512) {
        int il = i / 36, pool = i - il * 36;
        float m = s_conv[il][pool][0];
#pragma unroll
        for (int p = 1; p < 9; p++) m = fmaxf(m, s_conv[il][pool][p]);
        s_hs[il][pool] = fmaxf(m, 0.0f);
    }
    __syncthreads();

    // 36->6 linear per image
    if (t < 120) {
        int il = t / 6, d = t % 6;
        float s = __ldg(lb + d);
#pragma unroll
        for (int i = 0; i < 36; i++) s += s_hs[il][i] * __ldg(lw + i * 6 + d);
        s_feat[il][d] = s;
    }
    if (t >= 128 && t < 248) {           // concurrent: load pos
        int tt = t - 128;
        int fv = tt / 6, d = tt % 6;
        r_ps[fv][d] = pos[(n * 20 + fv) * 6 + d];
    }
    __syncthreads();

    // ---------------- graph ops ----------------
    if (t < 20) {
        float a = 0.0f, bb = 0.0f;
#pragma unroll
        for (int k = 0; k < 6; k++) {
            a  += s_feat[t][k] * wfc_w[k]      + r_ps[t][k] * wfc_w[6 + k];
            bb += s_feat[t][k] * wfc_w[12 + k] + r_ps[t][k] * wfc_w[18 + k];
        }
        r_asrc[t] = a;
        r_btgt[t] = bb;
    }
    if (t >= 128 && t < 248) {
        int tt = t - 128;
        int fv = tt / 6, d = tt % 6;
        float s = fm_b[d];
#pragma unroll
        for (int k = 0; k < 6; k++) s += r_ps[fv][k] * fm_w[k * 6 + d];
        r_pm[fv][d] = s;
    }
    __syncthreads();

    if (t < 120) {
        int fv = t / 6, d = t % 6;
        int f = fv / 4, tv = fv % 4;
        float bias = wfc_b[0];
        float agg = 0.0f;
#pragma unroll
        for (int s = 0; s < 4; s++) {
            float z  = r_asrc[f * 4 + s] + r_btgt[f * 4 + tv] + bias;
            float lk = 1.0f / (1.0f + expf(-z));
            float m  = lk + attmap[((n * 5 + f) * 4 + s) * 4 + tv];
            agg += m * r_pm[f * 4 + s][d];
        }
        if (f > 0) {
            float lm = lm_b[d];
#pragma unroll
            for (int k = 0; k < 6; k++) lm += r_ps[(f - 1) * 4 + tv][k] * lm_w[k * 6 + d];
            agg += lm;
        }
        r_inp[fv * 12 + d]     = s_feat[fv][d];
        r_inp[fv * 12 + 6 + d] = agg;
    }
    __syncthreads();

    // fc1: 240x120 split over 2 halves of the input dim
    if (t < 240) {
        int half = t / 120, j = t - half * 120;
        int i0 = half * 120;
        float s = 0.0f;
#pragma unroll 12
        for (int i = 0; i < 120; i++)
            s += r_inp[i0 + i] * __ldg(fc1_w + (i0 + i) * 120 + j);
        r_part[t] = s;
    }
    __syncthreads();
    if (t < 120) r_r1[t] = fmaxf(r_part[t] + r_part[120 + t] + __ldg(fc1_b + t), 0.0f);
    __syncthreads();

    // fc2: 120x60 split over 2 halves
    if (t < 120) {
        int half = t / 60, j = t - half * 60;
        int i0 = half * 60;
        float s = 0.0f;
#pragma unroll 12
        for (int i = 0; i < 60; i++)
            s += r_r1[i0 + i] * __ldg(fc2_w + (i0 + i) * 60 + j);
        r_part[t] = s;
    }
    __syncthreads();
    if (t < 60) r_r2[t] = fmaxf(r_part[t] + r_part[60 + t] + __ldg(fc2_b + t), 0.0f);
    __syncthreads();

    if (t < 6) {
        float s = __ldg(fc3_b + t);
#pragma unroll
        for (int i = 0; i < 60; i++) s += r_r2[i] * __ldg(fc3_w + i * 6 + t);
        out[n * 6 + t] = s;
    }
}

// ---------------------------------------------------------------------------
extern "C" void kernel_launch(void* const* d_in, const int* in_sizes, int n_in,
                              void* d_out, int out_size)
{
    const float* nodes   = (const float*)d_in[0];
    const float* pos     = (const float*)d_in[1];
    const float* attmap  = (const float*)d_in[2];
    const float* conv1_w = (const float*)d_in[4];
    const float* conv1_b = (const float*)d_in[5];
    const float* conv2_w = (const float*)d_in[6];
    const float* conv2_b = (const float*)d_in[7];
    const float* lin_w   = (const float*)d_in[8];
    const float* lin_b   = (const float*)d_in[9];
    const float* wfc_w   = (const float*)d_in[10];
    const float* wfc_b   = (const float*)d_in[11];
    const float* fm_w    = (const float*)d_in[12];
    const float* fm_b    = (const float*)d_in[13];
    const float* lm_w    = (const float*)d_in[14];
    const float* lm_b    = (const float*)d_in[15];
    const float* fc1_w   = (const float*)d_in[16];
    const float* fc1_b   = (const float*)d_in[17];
    const float* fc2_w   = (const float*)d_in[18];
    const float* fc2_b   = (const float*)d_in[19];
    const float* fc3_w   = (const float*)d_in[20];
    const float* fc3_b   = (const float*)d_in[21];
    float* out = (float*)d_out;

    conv1_pool_kernel<<<NBLK1, 256>>>(nodes, conv1_w, conv1_b);
    epilogue_kernel<<<16, 512>>>(pos, attmap, conv2_w, conv2_b,
                                 lin_w, lin_b, wfc_w, wfc_b, fm_w, fm_b,
                                 lm_w, lm_b, fc1_w, fc1_b, fc2_w, fc2_b,
                                 fc3_w, fc3_b, out);
}

// round 10
// speedup vs baseline: 1.2698x; 1.2698x over previous
#include <cuda_runtime.h>
#include <math.h>

// ---------------------------------------------------------------------------
// Shapes: N=16, F=5, V=4 -> 320 images of 3x224x224
// conv1: 3->3, 3x3, s2: 224->111 ; maxpool3/3 -> 37 ; relu
// conv2: 3->1, 3x3, s2: 37->18   ; maxpool3/3 -> 6  ; relu
// flatten 36 -> linear -> feat[320,6]; graph ops + MLP -> [16,6]
//
// K1: conv1+pool+relu, 1712x256, one output/thread (proven DRAM plateau).
// K2: 320 blocks x 256 thr (all resident). Block = image: coop float4 tile
//     load -> smem, conv2+pool+linear from smem -> g_feat. Ticket: last 16
//     blocks spin briefly, then run graph ops + readout with chunked-float4
//     MLP (short independent load chains). R8 lesson: the epilogue is load-
//     latency-chain bound; every phase here keeps loads independent/batched.
// R9 bug fixed: tile-load loop now covers all 1027 float4 (was 1024).
// ---------------------------------------------------------------------------

#define NIMG 320
#define H1_STRIDE 4108               // 3*1369 padded to /4 for float4 loads
#define TOTAL1 (NIMG * 1369)
#define NBLK1 1712

__device__ float g_h1[NIMG * H1_STRIDE];
__device__ float g_feat[NIMG * 6];
__device__ int g_cnt = 0, g_done = 0;

// ---------------- Kernel 1: conv1 + maxpool3 + relu ------------------------
__global__ __launch_bounds__(256, 3)
void conv1_pool_kernel(const float* __restrict__ nodes,
                       const float* __restrict__ w,   // [3,3,3,3] OIHW
                       const float* __restrict__ b)   // [3]
{
    __shared__ float sw[81];
    __shared__ float sb[3];
    int tid = threadIdx.x;
    if (tid < 81) sw[tid] = w[tid];
    if (tid < 3)  sb[tid] = b[tid];
    __syncthreads();

    int idx = blockIdx.x * 256 + tid;
    if (idx >= TOTAL1) return;
    int px  = idx % 37;
    int rem = idx / 37;
    int py  = rem % 37;
    int img = rem / 37;

    const float* base = nodes + (size_t)img * 150528
                              + (size_t)(6 * py) * 224 + 6 * px;

    float acc[9][3];
#pragma unroll
    for (int p = 0; p < 9; p++) {
        acc[p][0] = sb[0]; acc[p][1] = sb[1]; acc[p][2] = sb[2];
    }

#pragma unroll
    for (int ic = 0; ic < 3; ic++) {
        const float* chan = base + ic * 50176;
        float2 p2[7][4];
#pragma unroll
        for (int r = 0; r < 7; r++) {
            const float* rp = chan + r * 224;
            p2[r][0] = *(const float2*)(rp);
            p2[r][1] = *(const float2*)(rp + 2);
            p2[r][2] = *(const float2*)(rp + 4);
            p2[r][3] = *(const float2*)(rp + 6);
        }
#pragma unroll
        for (int ky = 0; ky < 3; ky++)
#pragma unroll
            for (int kx = 0; kx < 3; kx++) {
                float w0 = sw[ic * 9 + ky * 3 + kx];
                float w1 = sw[27 + ic * 9 + ky * 3 + kx];
                float w2 = sw[54 + ic * 9 + ky * 3 + kx];
#pragma unroll
                for (int cy = 0; cy < 3; cy++)
#pragma unroll
                    for (int cx = 0; cx < 3; cx++) {
                        int col = 2 * cx + kx;
                        float v = (col & 1) ? p2[2 * cy + ky][col >> 1].y
                                            : p2[2 * cy + ky][col >> 1].x;
                        acc[cy * 3 + cx][0] += v * w0;
                        acc[cy * 3 + cx][1] += v * w1;
                        acc[cy * 3 + cx][2] += v * w2;
                    }
            }
    }

#pragma unroll
    for (int oc = 0; oc < 3; oc++) {
        float m = acc[0][oc];
#pragma unroll
        for (int p = 1; p < 9; p++) m = fmaxf(m, acc[p][oc]);
        m = fmaxf(m, 0.0f);
        g_h1[(size_t)img * H1_STRIDE + oc * 1369 + py * 37 + px] = m;
    }
}

// ---------------- Kernel 2: epilogue, 320 blocks, ticketed readout ---------
__global__ __launch_bounds__(256)
void epilogue_kernel(const float* __restrict__ pos,     // [16,5,4,6]
                     const float* __restrict__ attmap,  // [16,5,4,4]
                     const float* __restrict__ c2w, const float* __restrict__ c2b,
                     const float* __restrict__ lw,  const float* __restrict__ lb,
                     const float* __restrict__ wfc_w, const float* __restrict__ wfc_b,
                     const float* __restrict__ fm_w,  const float* __restrict__ fm_b,
                     const float* __restrict__ lm_w,  const float* __restrict__ lm_b,
                     const float* __restrict__ fc1_w, const float* __restrict__ fc1_b,
                     const float* __restrict__ fc2_w, const float* __restrict__ fc2_b,
                     const float* __restrict__ fc3_w, const float* __restrict__ fc3_b,
                     float* __restrict__ out)           // [16,6]
{
    __shared__ float tile[H1_STRIDE];     // 16.4 KB, [ch*1369 + r*37 + c]
    __shared__ float sw2[27];
    __shared__ float s_conv[36][9];
    __shared__ float s_hs[36];
    __shared__ int   s_tick;
    __shared__ float r_feat[20][6];
    __shared__ float r_ps[20][6];
    __shared__ float r_asrc[20];
    __shared__ float r_btgt[20];
    __shared__ float r_pm[20][6];
    __shared__ float r_inp[240];
    __shared__ float4 r_p4[8][30];        // fc1 partials
    __shared__ float4 r_p4b[4][15];       // fc2 partials
    __shared__ float r_r1[120];
    __shared__ float r_r2[60];

    const int img = blockIdx.x;
    const int t   = threadIdx.x;
    if (t < 27) sw2[t] = c2w[t];

    // coalesced float4 tile load: 1027 float4 / 256 threads (independent)
    {
        const float4* src = (const float4*)(g_h1 + (size_t)img * H1_STRIDE);
        float4* dst = (float4*)tile;
#pragma unroll
        for (int k = 0; k < 5; k++) {     // FIX: 5 rounds covers 1027
            int i = t + k * 256;
            if (i < 1027) dst[i] = src[i];
        }
    }
    __syncthreads();

    // conv2(s2): 324 positions; explicit 27-value smem prefetch (batched LDS)
    for (int posn = t; posn < 324; posn += 256) {
        int pool = posn / 9, cp = posn - pool * 9;
        int py = pool / 6, px = pool - py * 6;
        int cy = 3 * py + cp / 3;
        int cx = 3 * px + cp % 3;
        const float* src = tile + (2 * cy) * 37 + 2 * cx;
        float v[27];
#pragma unroll
        for (int ic = 0; ic < 3; ic++)
#pragma unroll
            for (int ky = 0; ky < 3; ky++)
#pragma unroll
                for (int kx = 0; kx < 3; kx++)
                    v[ic * 9 + ky * 3 + kx] = src[ic * 1369 + ky * 37 + kx];
        float s = __ldg(c2b);
#pragma unroll
        for (int i = 0; i < 27; i++) s += v[i] * sw2[i];
        s_conv[pool][cp] = s;
    }
    __syncthreads();

    if (t < 36) {
        float m = s_conv[t][0];
#pragma unroll
        for (int p = 1; p < 9; p++) m = fmaxf(m, s_conv[t][p]);
        s_hs[t] = fmaxf(m, 0.0f);
    }
    __syncthreads();
    if (t < 6) {
        float s = __ldg(lb + t);
#pragma unroll
        for (int i = 0; i < 36; i++) s += s_hs[i] * __ldg(lw + i * 6 + t);
        g_feat[img * 6 + t] = s;
    }
    __syncthreads();

    if (t == 0) {
        __threadfence();                 // release g_feat
        s_tick = atomicAdd(&g_cnt, 1);
    }
    __syncthreads();
    int tick = s_tick;
    if (tick < NIMG - 16) return;        // not one of the last 16 finishers

    const int n = tick - (NIMG - 16);
    if (t == 0) {
        while (atomicAdd(&g_cnt, 0) < NIMG) __nanosleep(64);
        __threadfence();                 // acquire
    }
    __syncthreads();

    // ---------------- graph ops + readout MLP ----------------
    if (t < 120) {
        int fv = t / 6, d = t % 6;
        r_feat[fv][d] = g_feat[(n * 20 + fv) * 6 + d];
        r_ps[fv][d]   = pos[(n * 20 + fv) * 6 + d];
    }
    __syncthreads();

    if (t < 20) {
        float a = 0.0f, bb = 0.0f;
#pragma unroll
        for (int k = 0; k < 6; k++) {
            a  += r_feat[t][k] * wfc_w[k]      + r_ps[t][k] * wfc_w[6 + k];
            bb += r_feat[t][k] * wfc_w[12 + k] + r_ps[t][k] * wfc_w[18 + k];
        }
        r_asrc[t] = a;
        r_btgt[t] = bb;
    }
    if (t >= 128 && t < 248) {
        int tt = t - 128;
        int fv = tt / 6, d = tt % 6;
        float s = fm_b[d];
#pragma unroll
        for (int k = 0; k < 6; k++) s += r_ps[fv][k] * fm_w[k * 6 + d];
        r_pm[fv][d] = s;
    }
    __syncthreads();

    if (t < 120) {
        int fv = t / 6, d = t % 6;
        int f = fv / 4, tv = fv % 4;
        float bias = wfc_b[0];
        float agg = 0.0f;
#pragma unroll
        for (int s = 0; s < 4; s++) {
            float z  = r_asrc[f * 4 + s] + r_btgt[f * 4 + tv] + bias;
            float lk = 1.0f / (1.0f + expf(-z));
            float m  = lk + attmap[((n * 5 + f) * 4 + s) * 4 + tv];
            agg += m * r_pm[f * 4 + s][d];
        }
        if (f > 0) {
            float lm = lm_b[d];
#pragma unroll
            for (int k = 0; k < 6; k++) lm += r_ps[(f - 1) * 4 + tv][k] * lm_w[k * 6 + d];
            agg += lm;
        }
        r_inp[fv * 12 + d]     = r_feat[fv][d];
        r_inp[fv * 12 + 6 + d] = agg;
    }
    __syncthreads();

    // fc1 (240x120): 8 input-chunks x 30 output-quads; 30-deep float4 chains
    if (t < 240) {
        int c = t / 30, q = t - (t / 30) * 30;
        const float4* wrow = (const float4*)fc1_w;   // 30 float4 per row
        float4 a = make_float4(0.f, 0.f, 0.f, 0.f);
#pragma unroll
        for (int i = 0; i < 30; i++) {
            float  x = r_inp[c * 30 + i];
            float4 w = __ldg(wrow + (c * 30 + i) * 30 + q);
            a.x += x * w.x; a.y += x * w.y; a.z += x * w.z; a.w += x * w.w;
        }
        r_p4[c][q] = a;
    }
    __syncthreads();
    if (t < 120) {
        int q = t >> 2, comp = t & 3;
        float s = __ldg(fc1_b + t);
#pragma unroll
        for (int c = 0; c < 8; c++) {
            float4 p = r_p4[c][q];
            s += (comp == 0) ? p.x : (comp == 1) ? p.y : (comp == 2) ? p.z : p.w;
        }
        r_r1[t] = fmaxf(s, 0.0f);
    }
    __syncthreads();

    // fc2 (120x60): 4 chunks x 15 quads; 30-deep float4 chains
    if (t < 60) {
        int c = t / 15, q = t - (t / 15) * 15;
        const float4* wrow = (const float4*)fc2_w;   // 15 float4 per row
        float4 a = make_float4(0.f, 0.f, 0.f, 0.f);
#pragma unroll
        for (int i = 0; i < 30; i++) {
            float  x = r_r1[c * 30 + i];
            float4 w = __ldg(wrow + (c * 30 + i) * 15 + q);
            a.x += x * w.x; a.y += x * w.y; a.z += x * w.z; a.w += x * w.w;
        }
        r_p4b[c][q] = a;
    }
    __syncthreads();
    if (t < 60) {
        int q = t >> 2, comp = t & 3;
        float s = __ldg(fc2_b + t);
#pragma unroll
        for (int c = 0; c < 4; c++) {
            float4 p = r_p4b[c][q];
            s += (comp == 0) ? p.x : (comp == 1) ? p.y : (comp == 2) ? p.z : p.w;
        }
        r_r2[t] = fmaxf(s, 0.0f);
    }
    __syncthreads();

    if (t < 6) {
        float s = __ldg(fc3_b + t);
#pragma unroll
        for (int i = 0; i < 60; i++) s += r_r2[i] * __ldg(fc3_w + i * 6 + t);
        out[n * 6 + t] = s;
    }
    __syncthreads();

    // deterministic counter reset for graph replay
    if (t == 0) {
        int r = atomicAdd(&g_done, 1);
        if (r == 15) {
            g_cnt = 0;
            __threadfence();
            g_done = 0;
        }
    }
}

// ---------------------------------------------------------------------------
extern "C" void kernel_launch(void* const* d_in, const int* in_sizes, int n_in,
                              void* d_out, int out_size)
{
    const float* nodes   = (const float*)d_in[0];
    const float* pos     = (const float*)d_in[1];
    const float* attmap  = (const float*)d_in[2];
    const float* conv1_w = (const float*)d_in[4];
    const float* conv1_b = (const float*)d_in[5];
    const float* conv2_w = (const float*)d_in[6];
    const float* conv2_b = (const float*)d_in[7];
    const float* lin_w   = (const float*)d_in[8];
    const float* lin_b   = (const float*)d_in[9];
    const float* wfc_w   = (const float*)d_in[10];
    const float* wfc_b   = (const float*)d_in[11];
    const float* fm_w    = (const float*)d_in[12];
    const float* fm_b    = (const float*)d_in[13];
    const float* lm_w    = (const float*)d_in[14];
    const float* lm_b    = (const float*)d_in[15];
    const float* fc1_w   = (const float*)d_in[16];
    const float* fc1_b   = (const float*)d_in[17];
    const float* fc2_w   = (const float*)d_in[18];
    const float* fc2_b   = (const float*)d_in[19];
    const float* fc3_w   = (const float*)d_in[20];
    const float* fc3_b   = (const float*)d_in[21];
    float* out = (float*)d_out;

    conv1_pool_kernel<<<NBLK1, 256>>>(nodes, conv1_w, conv1_b);
    epilogue_kernel<<<NIMG, 256>>>(pos, attmap, conv2_w, conv2_b,
                                   lin_w, lin_b, wfc_w, wfc_b, fm_w, fm_b,
                                   lm_w, lm_b, fc1_w, fc1_b, fc2_w, fc2_b,
                                   fc3_w, fc3_b, out);
}

// round 11
// speedup vs baseline: 1.3643x; 1.0744x over previous
#include <cuda_runtime.h>
#include <math.h>

// ---------------------------------------------------------------------------
// Shapes: N=16, F=5, V=4 -> 320 images of 3x224x224
// conv1: 3->3, 3x3, s2: 224->111 ; maxpool3/3 -> 37 ; relu
// conv2: 3->1, 3x3, s2: 37->18   ; maxpool3/3 -> 6  ; relu
// flatten 36 -> linear -> feat[320,6]; graph ops + MLP -> [16,6]
//
// SINGLE kernel, 16 + 1712 blocks x 256 threads.
//  - Blocks 16..1727: conv1, one output/thread (proven 37.6us shape). After
//    publishing h1, per-image last-arriver (atomic counter) runs conv2+pool+
//    linear for that image -> g_feat. No waiting: conv2 overlaps conv1.
//  - Blocks 0..15: spin on feat counter (16 parked slots, harmless per R5),
//    then each runs one sample's graph+readout MLP.
// R5/R7/R10 evidence: separate epilogue kernel costs ~22us regardless of
// content; in-kernel continuation costs ~1us. This removes the launch.
// ---------------------------------------------------------------------------

#define NIMG 320
#define H1S (3 * 1369)
#define TOTAL1 (NIMG * 1369)
#define NCONV 1712
#define NRD 16

__device__ float g_h1[NIMG * H1S];
__device__ float g_feat[NIMG * 6];
__device__ __align__(16) int g_imgcnt[NIMG];
__device__ int g_cnt2 = 0, g_done = 0;

__global__ __launch_bounds__(256, 3)
void fused_kernel(const float* __restrict__ nodes,
                  const float* __restrict__ pos,     // [16,5,4,6]
                  const float* __restrict__ attmap,  // [16,5,4,4]
                  const float* __restrict__ c1w, const float* __restrict__ c1b,
                  const float* __restrict__ c2w, const float* __restrict__ c2b,
                  const float* __restrict__ lw,  const float* __restrict__ lb,
                  const float* __restrict__ wfc_w, const float* __restrict__ wfc_b,
                  const float* __restrict__ fm_w,  const float* __restrict__ fm_b,
                  const float* __restrict__ lm_w,  const float* __restrict__ lm_b,
                  const float* __restrict__ fc1_w, const float* __restrict__ fc1_b,
                  const float* __restrict__ fc2_w, const float* __restrict__ fc2_b,
                  const float* __restrict__ fc3_w, const float* __restrict__ fc3_b,
                  float* __restrict__ out)           // [16,6]
{
    __shared__ float sw[81];
    __shared__ float sb[3];
    __shared__ float sw2[27];
    __shared__ float s_conv[36][9];
    __shared__ float s_hs[36];
    __shared__ int   s_img[2];
    __shared__ int   s_do;
    // readout scratch (blocks 0..15 only)
    __shared__ float r_feat[20][6];
    __shared__ float r_ps[20][6];
    __shared__ float r_asrc[20];
    __shared__ float r_btgt[20];
    __shared__ float r_pm[20][6];
    __shared__ float r_inp[240];
    __shared__ float4 r_p4[8][30];
    __shared__ float4 r_p4b[4][15];
    __shared__ float r_r1[120];
    __shared__ float r_r2[60];

    const int t = threadIdx.x;

    // ======================= READOUT BLOCKS (0..15) =========================
    if (blockIdx.x < NRD) {
        const int n = blockIdx.x;
        if (t == 0) {
            while (atomicAdd(&g_cnt2, 0) < NIMG) __nanosleep(128);
            __threadfence();             // acquire all g_feat
        }
        __syncthreads();
        __threadfence();

        if (t < 120) {
            int fv = t / 6, d = t % 6;
            r_feat[fv][d] = g_feat[(n * 20 + fv) * 6 + d];
            r_ps[fv][d]   = pos[(n * 20 + fv) * 6 + d];
        }
        __syncthreads();

        if (t < 20) {
            float a = 0.0f, bb = 0.0f;
#pragma unroll
            for (int k = 0; k < 6; k++) {
                a  += r_feat[t][k] * wfc_w[k]      + r_ps[t][k] * wfc_w[6 + k];
                bb += r_feat[t][k] * wfc_w[12 + k] + r_ps[t][k] * wfc_w[18 + k];
            }
            r_asrc[t] = a;
            r_btgt[t] = bb;
        }
        if (t >= 128 && t < 248) {
            int tt = t - 128;
            int fv = tt / 6, d = tt % 6;
            float s = fm_b[d];
#pragma unroll
            for (int k = 0; k < 6; k++) s += r_ps[fv][k] * fm_w[k * 6 + d];
            r_pm[fv][d] = s;
        }
        __syncthreads();

        if (t < 120) {
            int fv = t / 6, d = t % 6;
            int f = fv / 4, tv = fv % 4;
            float bias = wfc_b[0];
            float agg = 0.0f;
#pragma unroll
            for (int s = 0; s < 4; s++) {
                float z  = r_asrc[f * 4 + s] + r_btgt[f * 4 + tv] + bias;
                float lk = 1.0f / (1.0f + expf(-z));
                float m  = lk + attmap[((n * 5 + f) * 4 + s) * 4 + tv];
                agg += m * r_pm[f * 4 + s][d];
            }
            if (f > 0) {
                float lm = lm_b[d];
#pragma unroll
                for (int k = 0; k < 6; k++)
                    lm += r_ps[(f - 1) * 4 + tv][k] * lm_w[k * 6 + d];
                agg += lm;
            }
            r_inp[fv * 12 + d]     = r_feat[fv][d];
            r_inp[fv * 12 + 6 + d] = agg;
        }
        __syncthreads();

        // fc1 (240x120): 8 chunks x 30 quads, 30-deep independent float4
        if (t < 240) {
            int c = t / 30, q = t - (t / 30) * 30;
            const float4* wrow = (const float4*)fc1_w;
            float4 a = make_float4(0.f, 0.f, 0.f, 0.f);
#pragma unroll
            for (int i = 0; i < 30; i++) {
                float  x = r_inp[c * 30 + i];
                float4 w = __ldg(wrow + (c * 30 + i) * 30 + q);
                a.x += x * w.x; a.y += x * w.y; a.z += x * w.z; a.w += x * w.w;
            }
            r_p4[c][q] = a;
        }
        __syncthreads();
        if (t < 120) {
            int q = t >> 2, comp = t & 3;
            float s = __ldg(fc1_b + t);
#pragma unroll
            for (int c = 0; c < 8; c++) {
                float4 p = r_p4[c][q];
                s += (comp == 0) ? p.x : (comp == 1) ? p.y : (comp == 2) ? p.z : p.w;
            }
            r_r1[t] = fmaxf(s, 0.0f);
        }
        __syncthreads();

        // fc2 (120x60): 4 chunks x 15 quads
        if (t < 60) {
            int c = t / 15, q = t - (t / 15) * 15;
            const float4* wrow = (const float4*)fc2_w;
            float4 a = make_float4(0.f, 0.f, 0.f, 0.f);
#pragma unroll
            for (int i = 0; i < 30; i++) {
                float  x = r_r1[c * 30 + i];
                float4 w = __ldg(wrow + (c * 30 + i) * 15 + q);
                a.x += x * w.x; a.y += x * w.y; a.z += x * w.z; a.w += x * w.w;
            }
            r_p4b[c][q] = a;
        }
        __syncthreads();
        if (t < 60) {
            int q = t >> 2, comp = t & 3;
            float s = __ldg(fc2_b + t);
#pragma unroll
            for (int c = 0; c < 4; c++) {
                float4 p = r_p4b[c][q];
                s += (comp == 0) ? p.x : (comp == 1) ? p.y : (comp == 2) ? p.z : p.w;
            }
            r_r2[t] = fmaxf(s, 0.0f);
        }
        __syncthreads();

        if (t < 6) {
            float s = __ldg(fc3_b + t);
#pragma unroll
            for (int i = 0; i < 60; i++) s += r_r2[i] * __ldg(fc3_w + i * 6 + t);
            out[n * 6 + t] = s;
        }
        __syncthreads();

        if (t == 0) {                    // deterministic reset for graph replay
            int r = atomicAdd(&g_done, 1);
            if (r == 15) {
#pragma unroll 4
                for (int i = 0; i < NIMG; i += 4)
                    *(int4*)&g_imgcnt[i] = make_int4(0, 0, 0, 0);
                g_cnt2 = 0;
                __threadfence();
                g_done = 0;
            }
        }
        return;
    }

    // ======================= CONV BLOCKS (16..1727) =========================
    if (t < 81) sw[t] = c1w[t];
    if (t < 3)  sb[t] = c1b[t];
    if (t >= 128 && t < 155) sw2[t - 128] = c2w[t - 128];
    __syncthreads();

    const int cb = blockIdx.x - NRD;
    const int lo = cb * 256;
    const int idx = lo + t;

    if (idx < TOTAL1) {
        int px  = idx % 37;
        int rem = idx / 37;
        int py  = rem % 37;
        int img = rem / 37;

        const float* base = nodes + (size_t)img * 150528
                                  + (size_t)(6 * py) * 224 + 6 * px;
        float acc[9][3];
#pragma unroll
        for (int p = 0; p < 9; p++) {
            acc[p][0] = sb[0]; acc[p][1] = sb[1]; acc[p][2] = sb[2];
        }
#pragma unroll
        for (int ic = 0; ic < 3; ic++) {
            const float* chan = base + ic * 50176;
            float2 p2[7][4];
#pragma unroll
            for (int r = 0; r < 7; r++) {
                const float* rp = chan + r * 224;
                p2[r][0] = *(const float2*)(rp);
                p2[r][1] = *(const float2*)(rp + 2);
                p2[r][2] = *(const float2*)(rp + 4);
                p2[r][3] = *(const float2*)(rp + 6);
            }
#pragma unroll
            for (int ky = 0; ky < 3; ky++)
#pragma unroll
                for (int kx = 0; kx < 3; kx++) {
                    float w0 = sw[ic * 9 + ky * 3 + kx];
                    float w1 = sw[27 + ic * 9 + ky * 3 + kx];
                    float w2 = sw[54 + ic * 9 + ky * 3 + kx];
#pragma unroll
                    for (int cy = 0; cy < 3; cy++)
#pragma unroll
                        for (int cx = 0; cx < 3; cx++) {
                            int col = 2 * cx + kx;
                            float v = (col & 1) ? p2[2 * cy + ky][col >> 1].y
                                                : p2[2 * cy + ky][col >> 1].x;
                            acc[cy * 3 + cx][0] += v * w0;
                            acc[cy * 3 + cx][1] += v * w1;
                            acc[cy * 3 + cx][2] += v * w2;
                        }
                }
        }
#pragma unroll
        for (int oc = 0; oc < 3; oc++) {
            float m = acc[0][oc];
#pragma unroll
            for (int p = 1; p < 9; p++) m = fmaxf(m, acc[p][oc]);
            m = fmaxf(m, 0.0f);
            g_h1[(size_t)img * H1S + oc * 1369 + py * 37 + px] = m;
        }
    }

    // publish h1, count contributions per image; last arriver does conv2
    __threadfence();
    __syncthreads();
    if (t == 0) {
        int hi = (lo + 256 < TOTAL1) ? lo + 256 : TOTAL1;
        int i0 = lo / 1369;
        int i1 = (hi - 1) / 1369;
        int mask = 0;
        s_img[0] = i0; s_img[1] = i1;
        if (i0 == i1) {
            int c = hi - lo;
            if (atomicAdd(&g_imgcnt[i0], c) + c == 1369) mask |= 1;
        } else {
            int c0 = (i0 + 1) * 1369 - lo;
            int c1 = hi - i1 * 1369;
            if (atomicAdd(&g_imgcnt[i0], c0) + c0 == 1369) mask |= 1;
            if (atomicAdd(&g_imgcnt[i1], c1) + c1 == 1369) mask |= 2;
        }
        s_do = mask;
    }
    __syncthreads();
    int doMask = s_do;
    if (doMask == 0) return;
    __threadfence();                     // acquire other contributors' h1

#pragma unroll
    for (int k = 0; k < 2; k++) {
        if (doMask & (1 << k)) {
            const int img = s_img[k];
            // conv2(s2): 324 positions / 256 threads, L2-hot batched loads
            for (int posn = t; posn < 324; posn += 256) {
                int pool = posn / 9, cp = posn - pool * 9;
                int py = pool / 6, px = pool - py * 6;
                int cy = 3 * py + cp / 3;
                int cx = 3 * px + cp % 3;
                const float* src = g_h1 + (size_t)img * H1S
                                        + (2 * cy) * 37 + 2 * cx;
                float v[27];
#pragma unroll
                for (int ic = 0; ic < 3; ic++)
#pragma unroll
                    for (int ky = 0; ky < 3; ky++)
#pragma unroll
                        for (int kx = 0; kx < 3; kx++)
                            v[ic * 9 + ky * 3 + kx] =
                                __ldg(src + ic * 1369 + ky * 37 + kx);
                float s = __ldg(c2b);
#pragma unroll
                for (int i = 0; i < 27; i++) s += v[i] * sw2[i];
                s_conv[pool][cp] = s;
            }
            __syncthreads();
            if (t < 36) {
                float m = s_conv[t][0];
#pragma unroll
                for (int p = 1; p < 9; p++) m = fmaxf(m, s_conv[t][p]);
                s_hs[t] = fmaxf(m, 0.0f);
            }
            __syncthreads();
            if (t < 6) {
                float s = __ldg(lb + t);
#pragma unroll
                for (int i = 0; i < 36; i++)
                    s += s_hs[i] * __ldg(lw + i * 6 + t);
                g_feat[img * 6 + t] = s;
            }
            __threadfence();
            __syncthreads();
            if (t == 0) atomicAdd(&g_cnt2, 1);
            __syncthreads();             // s_conv reuse if k=1 also fires
        }
    }
}

// ---------------------------------------------------------------------------
extern "C" void kernel_launch(void* const* d_in, const int* in_sizes, int n_in,
                              void* d_out, int out_size)
{
    const float* nodes   = (const float*)d_in[0];
    const float* pos     = (const float*)d_in[1];
    const float* attmap  = (const float*)d_in[2];
    const float* conv1_w = (const float*)d_in[4];
    const float* conv1_b = (const float*)d_in[5];
    const float* conv2_w = (const float*)d_in[6];
    const float* conv2_b = (const float*)d_in[7];
    const float* lin_w   = (const float*)d_in[8];
    const float* lin_b   = (const float*)d_in[9];
    const float* wfc_w   = (const float*)d_in[10];
    const float* wfc_b   = (const float*)d_in[11];
    const float* fm_w    = (const float*)d_in[12];
    const float* fm_b    = (const float*)d_in[13];
    const float* lm_w    = (const float*)d_in[14];
    const float* lm_b    = (const float*)d_in[15];
    const float* fc1_w   = (const float*)d_in[16];
    const float* fc1_b   = (const float*)d_in[17];
    const float* fc2_w   = (const float*)d_in[18];
    const float* fc2_b   = (const float*)d_in[19];
    const float* fc3_w   = (const float*)d_in[20];
    const float* fc3_b   = (const float*)d_in[21];
    float* out = (float*)d_out;

    fused_kernel<<<NRD + NCONV, 256>>>(nodes, pos, attmap,
                                       conv1_w, conv1_b, conv2_w, conv2_b,
                                       lin_w, lin_b, wfc_w, wfc_b, fm_w, fm_b,
                                       lm_w, lm_b, fc1_w, fc1_b, fc2_w, fc2_b,
                                       fc3_w, fc3_b, out);
}

// round 12
// speedup vs baseline: 1.4065x; 1.0309x over previous
#include <cuda_runtime.h>
#include <math.h>

// ---------------------------------------------------------------------------
// Shapes: N=16, F=5, V=4 -> 320 images of 3x224x224
// conv1: 3->3, 3x3, s2: 224->111 ; maxpool3/3 -> 37 ; relu
// conv2: 3->1, 3x3, s2: 37->18   ; maxpool3/3 -> 6  ; relu
// flatten 36 -> linear -> feat[320,6]; graph ops + MLP -> [16,6]
//
// K1: conv1+pool+relu, 1712x256, one output/thread (proven 37.6us shape).
// K2: 320 blocks x 256 thr. conv2+pool+linear per image -> g_feat; ticket;
//     last 16 blocks run graph+readout.
// R12 fix: spin-wait uses PLAIN VOLATILE LOADS, not atomicAdd(x,0) polling.
// RMW polling saturates the L2 atomic ALU for the counter address and
// starves producer increments (the invariant ~22us tail of R5-R11).
// ---------------------------------------------------------------------------

#define NIMG 320
#define H1S (3 * 1369)
#define TOTAL1 (NIMG * 1369)
#define NBLK1 1712

__device__ float g_h1[NIMG * H1S];
__device__ float g_feat[NIMG * 6];
__device__ int g_cnt = 0, g_done = 0;

// ---------------- Kernel 1: conv1 + maxpool3 + relu ------------------------
__global__ __launch_bounds__(256, 3)
void conv1_pool_kernel(const float* __restrict__ nodes,
                       const float* __restrict__ w,   // [3,3,3,3] OIHW
                       const float* __restrict__ b)   // [3]
{
    __shared__ float sw[81];
    __shared__ float sb[3];
    int tid = threadIdx.x;
    if (tid < 81) sw[tid] = w[tid];
    if (tid < 3)  sb[tid] = b[tid];
    __syncthreads();

    int idx = blockIdx.x * 256 + tid;
    if (idx >= TOTAL1) return;
    int px  = idx % 37;
    int rem = idx / 37;
    int py  = rem % 37;
    int img = rem / 37;

    const float* base = nodes + (size_t)img * 150528
                              + (size_t)(6 * py) * 224 + 6 * px;

    float acc[9][3];
#pragma unroll
    for (int p = 0; p < 9; p++) {
        acc[p][0] = sb[0]; acc[p][1] = sb[1]; acc[p][2] = sb[2];
    }

#pragma unroll
    for (int ic = 0; ic < 3; ic++) {
        const float* chan = base + ic * 50176;
        float2 p2[7][4];
#pragma unroll
        for (int r = 0; r < 7; r++) {
            const float* rp = chan + r * 224;
            p2[r][0] = *(const float2*)(rp);
            p2[r][1] = *(const float2*)(rp + 2);
            p2[r][2] = *(const float2*)(rp + 4);
            p2[r][3] = *(const float2*)(rp + 6);
        }
#pragma unroll
        for (int ky = 0; ky < 3; ky++)
#pragma unroll
            for (int kx = 0; kx < 3; kx++) {
                float w0 = sw[ic * 9 + ky * 3 + kx];
                float w1 = sw[27 + ic * 9 + ky * 3 + kx];
                float w2 = sw[54 + ic * 9 + ky * 3 + kx];
#pragma unroll
                for (int cy = 0; cy < 3; cy++)
#pragma unroll
                    for (int cx = 0; cx < 3; cx++) {
                        int col = 2 * cx + kx;
                        float v = (col & 1) ? p2[2 * cy + ky][col >> 1].y
                                            : p2[2 * cy + ky][col >> 1].x;
                        acc[cy * 3 + cx][0] += v * w0;
                        acc[cy * 3 + cx][1] += v * w1;
                        acc[cy * 3 + cx][2] += v * w2;
                    }
            }
    }

#pragma unroll
    for (int oc = 0; oc < 3; oc++) {
        float m = acc[0][oc];
#pragma unroll
        for (int p = 1; p < 9; p++) m = fmaxf(m, acc[p][oc]);
        m = fmaxf(m, 0.0f);
        g_h1[(size_t)img * H1S + oc * 1369 + py * 37 + px] = m;
    }
}

// ---------------- Kernel 2: epilogue, 320 blocks, ticketed readout ---------
__global__ __launch_bounds__(256)
void epilogue_kernel(const float* __restrict__ pos,     // [16,5,4,6]
                     const float* __restrict__ attmap,  // [16,5,4,4]
                     const float* __restrict__ c2w, const float* __restrict__ c2b,
                     const float* __restrict__ lw,  const float* __restrict__ lb,
                     const float* __restrict__ wfc_w, const float* __restrict__ wfc_b,
                     const float* __restrict__ fm_w,  const float* __restrict__ fm_b,
                     const float* __restrict__ lm_w,  const float* __restrict__ lm_b,
                     const float* __restrict__ fc1_w, const float* __restrict__ fc1_b,
                     const float* __restrict__ fc2_w, const float* __restrict__ fc2_b,
                     const float* __restrict__ fc3_w, const float* __restrict__ fc3_b,
                     float* __restrict__ out)           // [16,6]
{
    __shared__ float sw2[27];
    __shared__ float s_conv[36][9];
    __shared__ float s_hs[36];
    __shared__ int   s_tick;
    __shared__ float r_feat[20][6];
    __shared__ float r_ps[20][6];
    __shared__ float r_asrc[20];
    __shared__ float r_btgt[20];
    __shared__ float r_pm[20][6];
    __shared__ float r_inp[240];
    __shared__ float4 r_p4[8][30];
    __shared__ float4 r_p4b[4][15];
    __shared__ float r_r1[120];
    __shared__ float r_r2[60];

    const int img = blockIdx.x;
    const int t   = threadIdx.x;
    if (t < 27) sw2[t] = c2w[t];
    __syncthreads();

    // conv2(s2): 324 positions; batched 27-load prefetch from L2-hot g_h1
    for (int posn = t; posn < 324; posn += 256) {
        int pool = posn / 9, cp = posn - pool * 9;
        int py = pool / 6, px = pool - py * 6;
        int cy = 3 * py + cp / 3;
        int cx = 3 * px + cp % 3;
        const float* src = g_h1 + (size_t)img * H1S + (2 * cy) * 37 + 2 * cx;
        float v[27];
#pragma unroll
        for (int ic = 0; ic < 3; ic++)
#pragma unroll
            for (int ky = 0; ky < 3; ky++)
#pragma unroll
                for (int kx = 0; kx < 3; kx++)
                    v[ic * 9 + ky * 3 + kx] =
                        __ldg(src + ic * 1369 + ky * 37 + kx);
        float s = __ldg(c2b);
#pragma unroll
        for (int i = 0; i < 27; i++) s += v[i] * sw2[i];
        s_conv[pool][cp] = s;
    }
    __syncthreads();

    if (t < 36) {
        float m = s_conv[t][0];
#pragma unroll
        for (int p = 1; p < 9; p++) m = fmaxf(m, s_conv[t][p]);
        s_hs[t] = fmaxf(m, 0.0f);
    }
    __syncthreads();
    if (t < 6) {
        float s = __ldg(lb + t);
#pragma unroll
        for (int i = 0; i < 36; i++) s += s_hs[i] * __ldg(lw + i * 6 + t);
        g_feat[img * 6 + t] = s;
    }
    __syncthreads();

    if (t == 0) {
        __threadfence();                 // release g_feat
        s_tick = atomicAdd(&g_cnt, 1);   // ticket (needs return value)
    }
    __syncthreads();
    int tick = s_tick;
    if (tick < NIMG - 16) return;        // not one of the last 16 finishers

    const int n = tick - (NIMG - 16);
    if (t == 0) {
        // PLAIN LOAD polling — no L2 atomic-ALU serialization (R12 fix)
        while (*(volatile int*)&g_cnt < NIMG) __nanosleep(64);
        __threadfence();                 // acquire
    }
    __syncthreads();

    // ---------------- graph ops + readout MLP ----------------
    if (t < 120) {
        int fv = t / 6, d = t % 6;
        r_feat[fv][d] = g_feat[(n * 20 + fv) * 6 + d];
        r_ps[fv][d]   = pos[(n * 20 + fv) * 6 + d];
    }
    __syncthreads();

    if (t < 20) {
        float a = 0.0f, bb = 0.0f;
#pragma unroll
        for (int k = 0; k < 6; k++) {
            a  += r_feat[t][k] * wfc_w[k]      + r_ps[t][k] * wfc_w[6 + k];
            bb += r_feat[t][k] * wfc_w[12 + k] + r_ps[t][k] * wfc_w[18 + k];
        }
        r_asrc[t] = a;
        r_btgt[t] = bb;
    }
    if (t >= 128 && t < 248) {
        int tt = t - 128;
        int fv = tt / 6, d = tt % 6;
        float s = fm_b[d];
#pragma unroll
        for (int k = 0; k < 6; k++) s += r_ps[fv][k] * fm_w[k * 6 + d];
        r_pm[fv][d] = s;
    }
    __syncthreads();

    if (t < 120) {
        int fv = t / 6, d = t % 6;
        int f = fv / 4, tv = fv % 4;
        float bias = wfc_b[0];
        float agg = 0.0f;
#pragma unroll
        for (int s = 0; s < 4; s++) {
            float z  = r_asrc[f * 4 + s] + r_btgt[f * 4 + tv] + bias;
            float lk = 1.0f / (1.0f + expf(-z));
            float m  = lk + attmap[((n * 5 + f) * 4 + s) * 4 + tv];
            agg += m * r_pm[f * 4 + s][d];
        }
        if (f > 0) {
            float lm = lm_b[d];
#pragma unroll
            for (int k = 0; k < 6; k++)
                lm += r_ps[(f - 1) * 4 + tv][k] * lm_w[k * 6 + d];
            agg += lm;
        }
        r_inp[fv * 12 + d]     = r_feat[fv][d];
        r_inp[fv * 12 + 6 + d] = agg;
    }
    __syncthreads();

    // fc1 (240x120): 8 chunks x 30 quads; 30-deep independent float4 chains
    if (t < 240) {
        int c = t / 30, q = t - (t / 30) * 30;
        const float4* wrow = (const float4*)fc1_w;
        float4 a = make_float4(0.f, 0.f, 0.f, 0.f);
#pragma unroll
        for (int i = 0; i < 30; i++) {
            float  x = r_inp[c * 30 + i];
            float4 w = __ldg(wrow + (c * 30 + i) * 30 + q);
            a.x += x * w.x; a.y += x * w.y; a.z += x * w.z; a.w += x * w.w;
        }
        r_p4[c][q] = a;
    }
    __syncthreads();
    if (t < 120) {
        int q = t >> 2, comp = t & 3;
        float s = __ldg(fc1_b + t);
#pragma unroll
        for (int c = 0; c < 8; c++) {
            float4 p = r_p4[c][q];
            s += (comp == 0) ? p.x : (comp == 1) ? p.y : (comp == 2) ? p.z : p.w;
        }
        r_r1[t] = fmaxf(s, 0.0f);
    }
    __syncthreads();

    // fc2 (120x60): 4 chunks x 15 quads
    if (t < 60) {
        int c = t / 15, q = t - (t / 15) * 15;
        const float4* wrow = (const float4*)fc2_w;
        float4 a = make_float4(0.f, 0.f, 0.f, 0.f);
#pragma unroll
        for (int i = 0; i < 30; i++) {
            float  x = r_r1[c * 30 + i];
            float4 w = __ldg(wrow + (c * 30 + i) * 15 + q);
            a.x += x * w.x; a.y += x * w.y; a.z += x * w.z; a.w += x * w.w;
        }
        r_p4b[c][q] = a;
    }
    __syncthreads();
    if (t < 60) {
        int q = t >> 2, comp = t & 3;
        float s = __ldg(fc2_b + t);
#pragma unroll
        for (int c = 0; c < 4; c++) {
            float4 p = r_p4b[c][q];
            s += (comp == 0) ? p.x : (comp == 1) ? p.y : (comp == 2) ? p.z : p.w;
        }
        r_r2[t] = fmaxf(s, 0.0f);
    }
    __syncthreads();

    if (t < 6) {
        float s = __ldg(fc3_b + t);
#pragma unroll
        for (int i = 0; i < 60; i++) s += r_r2[i] * __ldg(fc3_w + i * 6 + t);
        out[n * 6 + t] = s;
    }
    __syncthreads();

    // deterministic counter reset for graph replay
    if (t == 0) {
        int r = atomicAdd(&g_done, 1);
        if (r == 15) {
            g_cnt = 0;
            __threadfence();
            g_done = 0;
        }
    }
}

// ---------------------------------------------------------------------------
extern "C" void kernel_launch(void* const* d_in, const int* in_sizes, int n_in,
                              void* d_out, int out_size)
{
    const float* nodes   = (const float*)d_in[0];
    const float* pos     = (const float*)d_in[1];
    const float* attmap  = (const float*)d_in[2];
    const float* conv1_w = (const float*)d_in[4];
    const float* conv1_b = (const float*)d_in[5];
    const float* conv2_w = (const float*)d_in[6];
    const float* conv2_b = (const float*)d_in[7];
    const float* lin_w   = (const float*)d_in[8];
    const float* lin_b   = (const float*)d_in[9];
    const float* wfc_w   = (const float*)d_in[10];
    const float* wfc_b   = (const float*)d_in[11];
    const float* fm_w    = (const float*)d_in[12];
    const float* fm_b    = (const float*)d_in[13];
    const float* lm_w    = (const float*)d_in[14];
    const float* lm_b    = (const float*)d_in[15];
    const float* fc1_w   = (const float*)d_in[16];
    const float* fc1_b   = (const float*)d_in[17];
    const float* fc2_w   = (const float*)d_in[18];
    const float* fc2_b   = (const float*)d_in[19];
    const float* fc3_w   = (const float*)d_in[20];
    const float* fc3_b   = (const float*)d_in[21];
    float* out = (float*)d_out;

    conv1_pool_kernel<<<NBLK1, 256>>>(nodes, conv1_w, conv1_b);
    epilogue_kernel<<<NIMG, 256>>>(pos, attmap, conv2_w, conv2_b,
                                   lin_w, lin_b, wfc_w, wfc_b, fm_w, fm_b,
                                   lm_w, lm_b, fc1_w, fc1_b, fc2_w, fc2_b,
                                   fc3_w, fc3_b, out);
}

// round 13
// speedup vs baseline: 1.4110x; 1.0032x over previous
#include <cuda_runtime.h>
#include <math.h>

// ---------------------------------------------------------------------------
// Shapes: N=16, F=5, V=4 -> 320 images of 3x224x224
// conv1: 3->3, 3x3, s2: 224->111 ; maxpool3/3 -> 37 ; relu
// conv2: 3->1, 3x3, s2: 37->18   ; maxpool3/3 -> 6  ; relu
// flatten 36 -> linear -> feat[320,6]; graph ops + MLP -> [16,6]
//
// K1: conv1+pool+relu, 1712x256 (proven 37.6us shape). Stride padded to 4108.
// K2: 320 blocks. Block img: smem-tile conv2+pool+linear -> g_feat, bump
//     per-sample counter g_scnt[img/20]. Blocks 0..15 then: pos-only
//     precompute (overlaps producers), busy-poll ONLY their sample's counter
//     (20 producers, not 320), then 8 short phases of readout.
// R13: kill the global 320-wide rendezvous + __nanosleep (the ghost's last
// surviving suspects). Per-sample counters reset by their consumer.
// ---------------------------------------------------------------------------

#define NIMG 320
#define H1S 4108                     // 3*1369 padded for float4
#define TOTAL1 (NIMG * 1369)
#define NBLK1 1712

__device__ float g_h1[NIMG * H1S];
__device__ float g_feat[NIMG * 6];
__device__ int g_scnt[16];           // zero-init; each replay returns it to 0

// ---------------- Kernel 1: conv1 + maxpool3 + relu ------------------------
__global__ __launch_bounds__(256, 3)
void conv1_pool_kernel(const float* __restrict__ nodes,
                       const float* __restrict__ w,   // [3,3,3,3] OIHW
                       const float* __restrict__ b)   // [3]
{
    __shared__ float sw[81];
    __shared__ float sb[3];
    int tid = threadIdx.x;
    if (tid < 81) sw[tid] = w[tid];
    if (tid < 3)  sb[tid] = b[tid];
    __syncthreads();

    int idx = blockIdx.x * 256 + tid;
    if (idx >= TOTAL1) return;
    int px  = idx % 37;
    int rem = idx / 37;
    int py  = rem % 37;
    int img = rem / 37;

    const float* base = nodes + (size_t)img * 150528
                              + (size_t)(6 * py) * 224 + 6 * px;

    float acc[9][3];
#pragma unroll
    for (int p = 0; p < 9; p++) {
        acc[p][0] = sb[0]; acc[p][1] = sb[1]; acc[p][2] = sb[2];
    }

#pragma unroll
    for (int ic = 0; ic < 3; ic++) {
        const float* chan = base + ic * 50176;
        float2 p2[7][4];
#pragma unroll
        for (int r = 0; r < 7; r++) {
            const float* rp = chan + r * 224;
            p2[r][0] = *(const float2*)(rp);
            p2[r][1] = *(const float2*)(rp + 2);
            p2[r][2] = *(const float2*)(rp + 4);
            p2[r][3] = *(const float2*)(rp + 6);
        }
#pragma unroll
        for (int ky = 0; ky < 3; ky++)
#pragma unroll
            for (int kx = 0; kx < 3; kx++) {
                float w0 = sw[ic * 9 + ky * 3 + kx];
                float w1 = sw[27 + ic * 9 + ky * 3 + kx];
                float w2 = sw[54 + ic * 9 + ky * 3 + kx];
#pragma unroll
                for (int cy = 0; cy < 3; cy++)
#pragma unroll
                    for (int cx = 0; cx < 3; cx++) {
                        int col = 2 * cx + kx;
                        float v = (col & 1) ? p2[2 * cy + ky][col >> 1].y
                                            : p2[2 * cy + ky][col >> 1].x;
                        acc[cy * 3 + cx][0] += v * w0;
                        acc[cy * 3 + cx][1] += v * w1;
                        acc[cy * 3 + cx][2] += v * w2;
                    }
            }
    }

#pragma unroll
    for (int oc = 0; oc < 3; oc++) {
        float m = acc[0][oc];
#pragma unroll
        for (int p = 1; p < 9; p++) m = fmaxf(m, acc[p][oc]);
        m = fmaxf(m, 0.0f);
        g_h1[(size_t)img * H1S + oc * 1369 + py * 37 + px] = m;
    }
}

// ---------------- Kernel 2: epilogue, per-sample rendezvous ----------------
__global__ __launch_bounds__(256)
void epilogue_kernel(const float* __restrict__ pos,     // [16,5,4,6]
                     const float* __restrict__ attmap,  // [16,5,4,4]
                     const float* __restrict__ c2w, const float* __restrict__ c2b,
                     const float* __restrict__ lw,  const float* __restrict__ lb,
                     const float* __restrict__ wfc_w, const float* __restrict__ wfc_b,
                     const float* __restrict__ fm_w,  const float* __restrict__ fm_b,
                     const float* __restrict__ lm_w,  const float* __restrict__ lm_b,
                     const float* __restrict__ fc1_w, const float* __restrict__ fc1_b,
                     const float* __restrict__ fc2_w, const float* __restrict__ fc2_b,
                     const float* __restrict__ fc3_w, const float* __restrict__ fc3_b,
                     float* __restrict__ out)           // [16,6]
{
    __shared__ float tile[H1S];          // 16.4 KB
    __shared__ float sw2[27];
    __shared__ float s_conv[36][9];
    __shared__ float s_hs[36];
    // readout smem (blocks 0..15)
    __shared__ float r_feat[20][6];
    __shared__ float r_ps[20][6];
    __shared__ float r_att[80];          // f*16 + s*4 + tv
    __shared__ float r_wfc[24];
    __shared__ float r_wb;
    __shared__ float r_asrc[20];
    __shared__ float r_btgt[20];
    __shared__ float r_pm[20][6];
    __shared__ float r_lmsg[20][6];
    __shared__ float r_inp[240];
    __shared__ float4 r_p4[8][30];
    __shared__ float4 r_p4b[4][15];
    __shared__ float r_r1[120];
    __shared__ float r_r2[60];

    const int img = blockIdx.x;
    const int t   = threadIdx.x;
    if (t < 27) sw2[t] = c2w[t];

    // coop float4 tile load (1027 float4, independent, coalesced)
    {
        const float4* src4 = (const float4*)(g_h1 + (size_t)img * H1S);
        float4* dst = (float4*)tile;
#pragma unroll
        for (int k = 0; k < 5; k++) {
            int i = t + k * 256;
            if (i < 1027) dst[i] = src4[i];
        }
    }
    __syncthreads();

    // conv2(s2) from smem
    for (int posn = t; posn < 324; posn += 256) {
        int pool = posn / 9, cp = posn - pool * 9;
        int py = pool / 6, px = pool - py * 6;
        int cy = 3 * py + cp / 3;
        int cx = 3 * px + cp % 3;
        const float* src = tile + (2 * cy) * 37 + 2 * cx;
        float v[27];
#pragma unroll
        for (int ic = 0; ic < 3; ic++)
#pragma unroll
            for (int ky = 0; ky < 3; ky++)
#pragma unroll
                for (int kx = 0; kx < 3; kx++)
                    v[ic * 9 + ky * 3 + kx] = src[ic * 1369 + ky * 37 + kx];
        float s = __ldg(c2b);
#pragma unroll
        for (int i = 0; i < 27; i++) s += v[i] * sw2[i];
        s_conv[pool][cp] = s;
    }
    __syncthreads();

    if (t < 36) {
        float m = s_conv[t][0];
#pragma unroll
        for (int p = 1; p < 9; p++) m = fmaxf(m, s_conv[t][p]);
        s_hs[t] = fmaxf(m, 0.0f);
    }
    __syncthreads();
    if (t < 6) {
        float s = __ldg(lb + t);
#pragma unroll
        for (int i = 0; i < 36; i++) s += s_hs[i] * __ldg(lw + i * 6 + t);
        g_feat[img * 6 + t] = s;
    }
    __syncthreads();
    if (t == 0) {
        __threadfence();                     // release feat
        atomicAdd(&g_scnt[img / 20], 1);     // bump my sample's counter
    }
    if (img >= 16) return;

    // =================== readout (blocks 0..15), sample n ===================
    const int n = img;

    // ---- pre-spin: pos-only loads (overlap with other producers) ----
    if (t < 120) {
        int fv = t / 6, d = t % 6;
        r_ps[fv][d] = pos[(n * 20 + fv) * 6 + d];
    }
    if (t >= 128 && t < 208) r_att[t - 128] = attmap[n * 80 + (t - 128)];
    if (t >= 208 && t < 232) r_wfc[t - 208] = wfc_w[t - 208];
    if (t == 232)            r_wb = wfc_b[0];
    __syncthreads();

    // ---- pre-spin: pos-only precompute ----
    if (t < 20) {                            // pos-part of edge logits
        float a = 0.0f, bb = 0.0f;
#pragma unroll
        for (int k = 0; k < 6; k++) {
            a  += r_ps[t][k] * r_wfc[6 + k];
            bb += r_ps[t][k] * r_wfc[18 + k];
        }
        r_asrc[t] = a;                       // pos part; feat part added later
        r_btgt[t] = bb;
    }
    if (t < 120) {                           // pm = pos @ fm_w + fm_b
        int fv = t / 6, d = t % 6;
        float s = __ldg(fm_b + d);
#pragma unroll
        for (int k = 0; k < 6; k++) s += r_ps[fv][k] * __ldg(fm_w + k * 6 + d);
        r_pm[fv][d] = s;
    }
    if (t >= 128 && t < 248) {               // last-frame message (pos-only)
        int tt = t - 128;
        int fv = tt / 6, d = tt % 6;
        int f = fv / 4, tv = fv % 4;
        float s = 0.0f;
        if (f > 0) {
            s = __ldg(lm_b + d);
#pragma unroll
            for (int k = 0; k < 6; k++)
                s += r_ps[(f - 1) * 4 + tv][k] * __ldg(lm_w + k * 6 + d);
        }
        r_lmsg[fv][d] = s;
    }
    __syncthreads();

    // ---- busy-poll ONLY this sample's 20 producers ----
    if (t == 0) {
        while (((volatile int*)g_scnt)[n] < 20) {}
        __threadfence();                     // acquire g_feat
    }
    __syncthreads();

    if (t < 120) {
        int fv = t / 6, d = t % 6;
        r_feat[fv][d] = g_feat[(n * 20 + fv) * 6 + d];
    }
    __syncthreads();
    if (t == 0) g_scnt[n] = 0;               // reset own counter for replay

    if (t < 20) {                            // finalize edge logit terms
        float a = r_asrc[t], bb = r_btgt[t];
#pragma unroll
        for (int k = 0; k < 6; k++) {
            a  += r_feat[t][k] * r_wfc[k];
            bb += r_feat[t][k] * r_wfc[12 + k];
        }
        r_asrc[t] = a;
        r_btgt[t] = bb;
    }
    __syncthreads();

    if (t < 120) {                           // aggregation + inp build
        int fv = t / 6, d = t % 6;
        int f = fv / 4, tv = fv % 4;
        float agg = r_lmsg[fv][d];
#pragma unroll
        for (int s = 0; s < 4; s++) {
            float z  = r_asrc[f * 4 + s] + r_btgt[f * 4 + tv] + r_wb;
            float lk = 1.0f / (1.0f + expf(-z));
            float m  = lk + r_att[f * 16 + s * 4 + tv];
            agg += m * r_pm[f * 4 + s][d];
        }
        r_inp[fv * 12 + d]     = r_feat[fv][d];
        r_inp[fv * 12 + 6 + d] = agg;
    }
    __syncthreads();

    // fc1 (240x120): 8 chunks x 30 quads; independent float4 chains
    if (t < 240) {
        int c = t / 30, q = t - (t / 30) * 30;
        const float4* wrow = (const float4*)fc1_w;
        float4 a = make_float4(0.f, 0.f, 0.f, 0.f);
#pragma unroll
        for (int i = 0; i < 30; i++) {
            float  x = r_inp[c * 30 + i];
            float4 w = __ldg(wrow + (c * 30 + i) * 30 + q);
            a.x += x * w.x; a.y += x * w.y; a.z += x * w.z; a.w += x * w.w;
        }
        r_p4[c][q] = a;
    }
    __syncthreads();
    if (t < 120) {
        int q = t >> 2, comp = t & 3;
        float s = __ldg(fc1_b + t);
#pragma unroll
        for (int c = 0; c < 8; c++) {
            float4 p = r_p4[c][q];
            s += (comp == 0) ? p.x : (comp == 1) ? p.y : (comp == 2) ? p.z : p.w;
        }
        r_r1[t] = fmaxf(s, 0.0f);
    }
    __syncthreads();

    // fc2 (120x60): 4 chunks x 15 quads
    if (t < 60) {
        int c = t / 15, q = t - (t / 15) * 15;
        const float4* wrow = (const float4*)fc2_w;
        float4 a = make_float4(0.f, 0.f, 0.f, 0.f);
#pragma unroll
        for (int i = 0; i < 30; i++) {
            float  x = r_r1[c * 30 + i];
            float4 w = __ldg(wrow + (c * 30 + i) * 15 + q);
            a.x += x * w.x; a.y += x * w.y; a.z += x * w.z; a.w += x * w.w;
        }
        r_p4b[c][q] = a;
    }
    __syncthreads();
    if (t < 60) {
        int q = t >> 2, comp = t & 3;
        float s = __ldg(fc2_b + t);
#pragma unroll
        for (int c = 0; c < 4; c++) {
            float4 p = r_p4b[c][q];
            s += (comp == 0) ? p.x : (comp == 1) ? p.y : (comp == 2) ? p.z : p.w;
        }
        r_r2[t] = fmaxf(s, 0.0f);
    }
    __syncthreads();

    if (t < 6) {
        float s = __ldg(fc3_b + t);
#pragma unroll
        for (int i = 0; i < 60; i++) s += r_r2[i] * __ldg(fc3_w + i * 6 + t);
        out[n * 6 + t] = s;
    }
}

// ---------------------------------------------------------------------------
extern "C" void kernel_launch(void* const* d_in, const int* in_sizes, int n_in,
                              void* d_out, int out_size)
{
    const float* nodes   = (const float*)d_in[0];
    const float* pos     = (const float*)d_in[1];
    const float* attmap  = (const float*)d_in[2];
    const float* conv1_w = (const float*)d_in[4];
    const float* conv1_b = (const float*)d_in[5];
    const float* conv2_w = (const float*)d_in[6];
    const float* conv2_b = (const float*)d_in[7];
    const float* lin_w   = (const float*)d_in[8];
    const float* lin_b   = (const float*)d_in[9];
    const float* wfc_w   = (const float*)d_in[10];
    const float* wfc_b   = (const float*)d_in[11];
    const float* fm_w    = (const float*)d_in[12];
    const float* fm_b    = (const float*)d_in[13];
    const float* lm_w    = (const float*)d_in[14];
    const float* lm_b    = (const float*)d_in[15];
    const float* fc1_w   = (const float*)d_in[16];
    const float* fc1_b   = (const float*)d_in[17];
    const float* fc2_w   = (const float*)d_in[18];
    const float* fc2_b   = (const float*)d_in[19];
    const float* fc3_w   = (const float*)d_in[20];
    const float* fc3_b   = (const float*)d_in[21];
    float* out = (float*)d_out;

    conv1_pool_kernel<<<NBLK1, 256>>>(nodes, conv1_w, conv1_b);
    epilogue_kernel<<<NIMG, 256>>>(pos, attmap, conv2_w, conv2_b,
                                   lin_w, lin_b, wfc_w, wfc_b, fm_w, fm_b,
                                   lm_w, lm_b, fc1_w, fc1_b, fc2_w, fc2_b,
                                   fc3_w, fc3_b, out);
}

// round 14
// speedup vs baseline: 1.4178x; 1.0048x over previous
#include <cuda_runtime.h>
#include <math.h>

// ---------------------------------------------------------------------------
// Shapes: N=16, F=5, V=4 -> 320 images of 3x224x224
// conv1: 3->3, 3x3, s2: 224->111 ; maxpool3/3 -> 37 ; relu
// conv2: 3->1, 3x3, s2: 37->18   ; maxpool3/3 -> 6  ; relu
// flatten 36 -> linear -> feat[320,6]; graph ops + MLP -> [16,6]
//
// R14: THREE kernels, ZERO in-kernel synchronization (no fences, atomics,
// or spins anywhere). Kernel boundaries provide ordering/visibility.
//  K1: conv1+pool+relu, 1712x256, one output/thread (proven shape).
//  K2: conv2+pool+linear, 320 blocks: float4 tile -> smem -> g_feat.
//  K3: readout, 16 blocks: chunked-float4 MLP.
// Controlled experiment: if the invariant ~22us epilogue ghost disappears,
// it was the producer-side __threadfence (CCTL.IVALL)/atomic/wait machinery.
// ---------------------------------------------------------------------------

#define NIMG 320
#define H1S 4108                     // 3*1369 padded to /4 for float4
#define TOTAL1 (NIMG * 1369)
#define NBLK1 1712

__device__ float g_h1[NIMG * H1S];
__device__ float g_feat[NIMG * 6];

// ---------------- Kernel 1: conv1 + maxpool3 + relu ------------------------
__global__ __launch_bounds__(256, 3)
void conv1_pool_kernel(const float* __restrict__ nodes,
                       const float* __restrict__ w,   // [3,3,3,3] OIHW
                       const float* __restrict__ b)   // [3]
{
    __shared__ float sw[81];
    __shared__ float sb[3];
    int tid = threadIdx.x;
    if (tid < 81) sw[tid] = w[tid];
    if (tid < 3)  sb[tid] = b[tid];
    __syncthreads();

    int idx = blockIdx.x * 256 + tid;
    if (idx >= TOTAL1) return;
    int px  = idx % 37;
    int rem = idx / 37;
    int py  = rem % 37;
    int img = rem / 37;

    const float* base = nodes + (size_t)img * 150528
                              + (size_t)(6 * py) * 224 + 6 * px;

    float acc[9][3];
#pragma unroll
    for (int p = 0; p < 9; p++) {
        acc[p][0] = sb[0]; acc[p][1] = sb[1]; acc[p][2] = sb[2];
    }

#pragma unroll
    for (int ic = 0; ic < 3; ic++) {
        const float* chan = base + ic * 50176;
        float2 p2[7][4];
#pragma unroll
        for (int r = 0; r < 7; r++) {
            const float* rp = chan + r * 224;
            p2[r][0] = *(const float2*)(rp);
            p2[r][1] = *(const float2*)(rp + 2);
            p2[r][2] = *(const float2*)(rp + 4);
            p2[r][3] = *(const float2*)(rp + 6);
        }
#pragma unroll
        for (int ky = 0; ky < 3; ky++)
#pragma unroll
            for (int kx = 0; kx < 3; kx++) {
                float w0 = sw[ic * 9 + ky * 3 + kx];
                float w1 = sw[27 + ic * 9 + ky * 3 + kx];
                float w2 = sw[54 + ic * 9 + ky * 3 + kx];
#pragma unroll
                for (int cy = 0; cy < 3; cy++)
#pragma unroll
                    for (int cx = 0; cx < 3; cx++) {
                        int col = 2 * cx + kx;
                        float v = (col & 1) ? p2[2 * cy + ky][col >> 1].y
                                            : p2[2 * cy + ky][col >> 1].x;
                        acc[cy * 3 + cx][0] += v * w0;
                        acc[cy * 3 + cx][1] += v * w1;
                        acc[cy * 3 + cx][2] += v * w2;
                    }
            }
    }

#pragma unroll
    for (int oc = 0; oc < 3; oc++) {
        float m = acc[0][oc];
#pragma unroll
        for (int p = 1; p < 9; p++) m = fmaxf(m, acc[p][oc]);
        m = fmaxf(m, 0.0f);
        g_h1[(size_t)img * H1S + oc * 1369 + py * 37 + px] = m;
    }
}

// ---------------- Kernel 2: conv2 + maxpool3 + relu + linear (pure) --------
__global__ __launch_bounds__(256)
void conv2_kernel(const float* __restrict__ c2w, const float* __restrict__ c2b,
                  const float* __restrict__ lw,  const float* __restrict__ lb)
{
    __shared__ float tile[H1S];          // 16.4 KB
    __shared__ float sw2[27];
    __shared__ float s_conv[36][9];
    __shared__ float s_hs[36];

    const int img = blockIdx.x;
    const int t   = threadIdx.x;
    if (t < 27) sw2[t] = c2w[t];

    // coop float4 tile load: 1027 float4, coalesced, independent
    {
        const float4* src4 = (const float4*)(g_h1 + (size_t)img * H1S);
        float4* dst = (float4*)tile;
#pragma unroll
        for (int k = 0; k < 5; k++) {
            int i = t + k * 256;
            if (i < 1027) dst[i] = src4[i];
        }
    }
    __syncthreads();

    // conv2(s2) from smem: 324 positions
    for (int posn = t; posn < 324; posn += 256) {
        int pool = posn / 9, cp = posn - pool * 9;
        int py = pool / 6, px = pool - py * 6;
        int cy = 3 * py + cp / 3;
        int cx = 3 * px + cp % 3;
        const float* src = tile + (2 * cy) * 37 + 2 * cx;
        float v[27];
#pragma unroll
        for (int ic = 0; ic < 3; ic++)
#pragma unroll
            for (int ky = 0; ky < 3; ky++)
#pragma unroll
                for (int kx = 0; kx < 3; kx++)
                    v[ic * 9 + ky * 3 + kx] = src[ic * 1369 + ky * 37 + kx];
        float s = __ldg(c2b);
#pragma unroll
        for (int i = 0; i < 27; i++) s += v[i] * sw2[i];
        s_conv[pool][cp] = s;
    }
    __syncthreads();

    if (t < 36) {
        float m = s_conv[t][0];
#pragma unroll
        for (int p = 1; p < 9; p++) m = fmaxf(m, s_conv[t][p]);
        s_hs[t] = fmaxf(m, 0.0f);
    }
    __syncthreads();
    if (t < 6) {
        float s = __ldg(lb + t);
#pragma unroll
        for (int i = 0; i < 36; i++) s += s_hs[i] * __ldg(lw + i * 6 + t);
        g_feat[img * 6 + t] = s;
    }
}

// ---------------- Kernel 3: graph ops + readout MLP (pure) -----------------
__global__ __launch_bounds__(256)
void readout_kernel(const float* __restrict__ pos,     // [16,5,4,6]
                    const float* __restrict__ attmap,  // [16,5,4,4]
                    const float* __restrict__ wfc_w, const float* __restrict__ wfc_b,
                    const float* __restrict__ fm_w,  const float* __restrict__ fm_b,
                    const float* __restrict__ lm_w,  const float* __restrict__ lm_b,
                    const float* __restrict__ fc1_w, const float* __restrict__ fc1_b,
                    const float* __restrict__ fc2_w, const float* __restrict__ fc2_b,
                    const float* __restrict__ fc3_w, const float* __restrict__ fc3_b,
                    float* __restrict__ out)           // [16,6]
{
    __shared__ float r_feat[20][6];
    __shared__ float r_ps[20][6];
    __shared__ float r_asrc[20];
    __shared__ float r_btgt[20];
    __shared__ float r_pm[20][6];
    __shared__ float r_inp[240];
    __shared__ float4 r_p4[8][30];
    __shared__ float4 r_p4b[4][15];
    __shared__ float r_r1[120];
    __shared__ float r_r2[60];

    const int n = blockIdx.x;
    const int t = threadIdx.x;

    if (t < 120) {
        int fv = t / 6, d = t % 6;
        r_feat[fv][d] = g_feat[(n * 20 + fv) * 6 + d];
        r_ps[fv][d]   = pos[(n * 20 + fv) * 6 + d];
    }
    __syncthreads();

    if (t < 20) {
        float a = 0.0f, bb = 0.0f;
#pragma unroll
        for (int k = 0; k < 6; k++) {
            a  += r_feat[t][k] * __ldg(wfc_w + k)      + r_ps[t][k] * __ldg(wfc_w + 6 + k);
            bb += r_feat[t][k] * __ldg(wfc_w + 12 + k) + r_ps[t][k] * __ldg(wfc_w + 18 + k);
        }
        r_asrc[t] = a;
        r_btgt[t] = bb;
    }
    if (t >= 128 && t < 248) {
        int tt = t - 128;
        int fv = tt / 6, d = tt % 6;
        float s = __ldg(fm_b + d);
#pragma unroll
        for (int k = 0; k < 6; k++) s += r_ps[fv][k] * __ldg(fm_w + k * 6 + d);
        r_pm[fv][d] = s;
    }
    __syncthreads();

    if (t < 120) {
        int fv = t / 6, d = t % 6;
        int f = fv / 4, tv = fv % 4;
        float bias = __ldg(wfc_b);
        float agg = 0.0f;
#pragma unroll
        for (int s = 0; s < 4; s++) {
            float z  = r_asrc[f * 4 + s] + r_btgt[f * 4 + tv] + bias;
            float lk = 1.0f / (1.0f + expf(-z));
            float m  = lk + __ldg(attmap + ((n * 5 + f) * 4 + s) * 4 + tv);
            agg += m * r_pm[f * 4 + s][d];
        }
        if (f > 0) {
            float lm = __ldg(lm_b + d);
#pragma unroll
            for (int k = 0; k < 6; k++)
                lm += r_ps[(f - 1) * 4 + tv][k] * __ldg(lm_w + k * 6 + d);
            agg += lm;
        }
        r_inp[fv * 12 + d]     = r_feat[fv][d];
        r_inp[fv * 12 + 6 + d] = agg;
    }
    __syncthreads();

    // fc1 (240x120): 8 chunks x 30 quads; 30-deep independent float4 chains
    if (t < 240) {
        int c = t / 30, q = t - (t / 30) * 30;
        const float4* wrow = (const float4*)fc1_w;
        float4 a = make_float4(0.f, 0.f, 0.f, 0.f);
#pragma unroll
        for (int i = 0; i < 30; i++) {
            float  x = r_inp[c * 30 + i];
            float4 w = __ldg(wrow + (c * 30 + i) * 30 + q);
            a.x += x * w.x; a.y += x * w.y; a.z += x * w.z; a.w += x * w.w;
        }
        r_p4[c][q] = a;
    }
    __syncthreads();
    if (t < 120) {
        int q = t >> 2, comp = t & 3;
        float s = __ldg(fc1_b + t);
#pragma unroll
        for (int c = 0; c < 8; c++) {
            float4 p = r_p4[c][q];
            s += (comp == 0) ? p.x : (comp == 1) ? p.y : (comp == 2) ? p.z : p.w;
        }
        r_r1[t] = fmaxf(s, 0.0f);
    }
    __syncthreads();

    // fc2 (120x60): 4 chunks x 15 quads
    if (t < 60) {
        int c = t / 15, q = t - (t / 15) * 15;
        const float4* wrow = (const float4*)fc2_w;
        float4 a = make_float4(0.f, 0.f, 0.f, 0.f);
#pragma unroll
        for (int i = 0; i < 30; i++) {
            float  x = r_r1[c * 30 + i];
            float4 w = __ldg(wrow + (c * 30 + i) * 15 + q);
            a.x += x * w.x; a.y += x * w.y; a.z += x * w.z; a.w += x * w.w;
        }
        r_p4b[c][q] = a;
    }
    __syncthreads();
    if (t < 60) {
        int q = t >> 2, comp = t & 3;
        float s = __ldg(fc2_b + t);
#pragma unroll
        for (int c = 0; c < 4; c++) {
            float4 p = r_p4b[c][q];
            s += (comp == 0) ? p.x : (comp == 1) ? p.y : (comp == 2) ? p.z : p.w;
        }
        r_r2[t] = fmaxf(s, 0.0f);
    }
    __syncthreads();

    if (t < 6) {
        float s = __ldg(fc3_b + t);
#pragma unroll
        for (int i = 0; i < 60; i++) s += r_r2[i] * __ldg(fc3_w + i * 6 + t);
        out[n * 6 + t] = s;
    }
}

// ---------------------------------------------------------------------------
extern "C" void kernel_launch(void* const* d_in, const int* in_sizes, int n_in,
                              void* d_out, int out_size)
{
    const float* nodes   = (const float*)d_in[0];
    const float* pos     = (const float*)d_in[1];
    const float* attmap  = (const float*)d_in[2];
    const float* conv1_w = (const float*)d_in[4];
    const float* conv1_b = (const float*)d_in[5];
    const float* conv2_w = (const float*)d_in[6];
    const float* conv2_b = (const float*)d_in[7];
    const float* lin_w   = (const float*)d_in[8];
    const float* lin_b   = (const float*)d_in[9];
    const float* wfc_w   = (const float*)d_in[10];
    const float* wfc_b   = (const float*)d_in[11];
    const float* fm_w    = (const float*)d_in[12];
    const float* fm_b    = (const float*)d_in[13];
    const float* lm_w    = (const float*)d_in[14];
    const float* lm_b    = (const float*)d_in[15];
    const float* fc1_w   = (const float*)d_in[16];
    const float* fc1_b   = (const float*)d_in[17];
    const float* fc2_w   = (const float*)d_in[18];
    const float* fc2_b   = (const float*)d_in[19];
    const float* fc3_w   = (const float*)d_in[20];
    const float* fc3_b   = (const float*)d_in[21];
    float* out = (float*)d_out;

    conv1_pool_kernel<<<NBLK1, 256>>>(nodes, conv1_w, conv1_b);
    conv2_kernel<<<NIMG, 256>>>(conv2_w, conv2_b, lin_w, lin_b);
    readout_kernel<<<16, 256>>>(pos, attmap, wfc_w, wfc_b, fm_w, fm_b,
                                lm_w, lm_b, fc1_w, fc1_b, fc2_w, fc2_b,
                                fc3_w, fc3_b, out);
}

// round 15
// speedup vs baseline: 1.4716x; 1.0379x over previous
#include <cuda_runtime.h>
#include <math.h>

// ---------------------------------------------------------------------------
// Shapes: N=16, F=5, V=4 -> 320 images of 3x224x224
// conv1: 3->3, 3x3, s2: 224->111 ; maxpool3/3 -> 37 ; relu
// conv2: 3->1, 3x3, s2: 37->18   ; maxpool3/3 -> 6  ; relu
// flatten 36 -> linear -> feat[320,6]; graph ops + MLP -> [16,6]
//
// R15: conv1 restructured for occupancy. Per-thread live state cut from
// 56-reg patch + 27 acc (80 regs, 3 blocks/SM) to 24-reg row-slab + 9 acc +
// 3 running-max (≈50 regs, launch_bounds(256,4) -> 32 warps/SM). In-flight
// loads scale with warps (M_max=55/warp >> per-thread need), so +33% warps
// should lift DRAM 66% -> ~80%. Epilogue = R7 verbatim (best total 57.9).
// ---------------------------------------------------------------------------

#define NIMG 320
#define H1S (3 * 1369)
#define TOTAL1 (NIMG * 1369)
#define NBLK1 1712

__device__ float g_h1[NIMG * H1S];
__device__ float g_feat[NIMG * 6];
__device__ int g_cnt = 0, g_done = 0;

// ---------------- Kernel 1: conv1 + maxpool3 + relu (low-reg form) ---------
__global__ __launch_bounds__(256, 4)
void conv1_pool_kernel(const float* __restrict__ nodes,
                       const float* __restrict__ w,   // [3,3,3,3] OIHW
                       const float* __restrict__ b)   // [3]
{
    __shared__ float sw[81];
    __shared__ float sb[3];
    int tid = threadIdx.x;
    if (tid < 81) sw[tid] = w[tid];
    if (tid < 3)  sb[tid] = b[tid];
    __syncthreads();

    int idx = blockIdx.x * 256 + tid;
    if (idx >= TOTAL1) return;
    int px  = idx % 37;
    int rem = idx / 37;
    int py  = rem % 37;
    int img = rem / 37;

    const float* base = nodes + (size_t)img * 150528
                              + (size_t)(6 * py) * 224 + 6 * px;

    float m0 = -1e30f, m1 = -1e30f, m2 = -1e30f;

#pragma unroll
    for (int cy = 0; cy < 3; cy++) {
        // accs for the 3 conv positions (cy, cx=0..2) x 3 output channels
        float a00 = sb[0], a01 = sb[1], a02 = sb[2];
        float a10 = sb[0], a11 = sb[1], a12 = sb[2];
        float a20 = sb[0], a21 = sb[1], a22 = sb[2];

#pragma unroll
        for (int ic = 0; ic < 3; ic++) {
            // 3-row x 8-col slab (rows 2cy..2cy+2), 12 independent float2 loads
            const float* rp = base + ic * 50176 + (2 * cy) * 224;
            float2 rr[3][4];
#pragma unroll
            for (int r = 0; r < 3; r++)
#pragma unroll
                for (int j = 0; j < 4; j++)
                    rr[r][j] = *(const float2*)(rp + r * 224 + 2 * j);

#pragma unroll
            for (int ky = 0; ky < 3; ky++)
#pragma unroll
                for (int kx = 0; kx < 3; kx++) {
                    float w0 = sw[ic * 9 + ky * 3 + kx];
                    float w1 = sw[27 + ic * 9 + ky * 3 + kx];
                    float w2 = sw[54 + ic * 9 + ky * 3 + kx];
                    int c0 = kx, c1 = 2 + kx, c2 = 4 + kx;
                    float v0 = (c0 & 1) ? rr[ky][c0 >> 1].y : rr[ky][c0 >> 1].x;
                    float v1 = (c1 & 1) ? rr[ky][c1 >> 1].y : rr[ky][c1 >> 1].x;
                    float v2 = (c2 & 1) ? rr[ky][c2 >> 1].y : rr[ky][c2 >> 1].x;
                    a00 += v0 * w0; a01 += v0 * w1; a02 += v0 * w2;
                    a10 += v1 * w0; a11 += v1 * w1; a12 += v1 * w2;
                    a20 += v2 * w0; a21 += v2 * w1; a22 += v2 * w2;
                }
        }
        m0 = fmaxf(m0, fmaxf(a00, fmaxf(a10, a20)));
        m1 = fmaxf(m1, fmaxf(a01, fmaxf(a11, a21)));
        m2 = fmaxf(m2, fmaxf(a02, fmaxf(a12, a22)));
    }

    float* dst = g_h1 + (size_t)img * H1S + py * 37 + px;
    dst[0]        = fmaxf(m0, 0.0f);
    dst[1369]     = fmaxf(m1, 0.0f);
    dst[2 * 1369] = fmaxf(m2, 0.0f);
}

// ---------------- Kernel 2: epilogue (R7 verbatim, best total) -------------
__global__ __launch_bounds__(256)
void epilogue_kernel(const float* __restrict__ pos,     // [16,5,4,6]
                     const float* __restrict__ attmap,  // [16,5,4,4]
                     const float* __restrict__ c2w, const float* __restrict__ c2b,
                     const float* __restrict__ lw,  const float* __restrict__ lb,
                     const float* __restrict__ wfc_w, const float* __restrict__ wfc_b,
                     const float* __restrict__ fm_w,  const float* __restrict__ fm_b,
                     const float* __restrict__ lm_w,  const float* __restrict__ lm_b,
                     const float* __restrict__ fc1_w, const float* __restrict__ fc1_b,
                     const float* __restrict__ fc2_w, const float* __restrict__ fc2_b,
                     const float* __restrict__ fc3_w, const float* __restrict__ fc3_b,
                     float* __restrict__ out)           // [16,6]
{
    __shared__ float sw2[27];
    __shared__ float s_conv[36][9];
    __shared__ float s_hs[36];
    __shared__ int   s_tick;
    __shared__ float r_feat[20][6];
    __shared__ float r_ps[20][6];
    __shared__ float r_asrc[20];
    __shared__ float r_btgt[20];
    __shared__ float r_pm[20][6];
    __shared__ float r_inp[240];
    __shared__ float r_part[240];
    __shared__ float r_r1[120];
    __shared__ float r_r2[60];

    const int img = blockIdx.x;
    const int t   = threadIdx.x;
    if (t < 27) sw2[t] = c2w[t];
    __syncthreads();

    for (int posn = t; posn < 324; posn += 256) {
        int pool = posn / 9, cp = posn - pool * 9;
        int py = pool / 6, px = pool - py * 6;
        int cy = 3 * py + cp / 3;
        int cx = 3 * px + cp % 3;
        const float* src = g_h1 + (size_t)img * H1S + (2 * cy) * 37 + 2 * cx;
        float s = __ldg(c2b);
#pragma unroll
        for (int ic = 0; ic < 3; ic++)
#pragma unroll
            for (int ky = 0; ky < 3; ky++)
#pragma unroll
                for (int kx = 0; kx < 3; kx++)
                    s += __ldg(src + ic * 1369 + ky * 37 + kx)
                         * sw2[ic * 9 + ky * 3 + kx];
        s_conv[pool][cp] = s;
    }
    __syncthreads();
    if (t < 36) {
        float m = s_conv[t][0];
#pragma unroll
        for (int p = 1; p < 9; p++) m = fmaxf(m, s_conv[t][p]);
        s_hs[t] = fmaxf(m, 0.0f);
    }
    __syncthreads();
    if (t < 6) {
        float s = __ldg(lb + t);
#pragma unroll
        for (int i = 0; i < 36; i++) s += s_hs[i] * __ldg(lw + i * 6 + t);
        g_feat[img * 6 + t] = s;
    }
    __syncthreads();

    if (t == 0) {
        __threadfence();
        s_tick = atomicAdd(&g_cnt, 1);
    }
    __syncthreads();
    int tick = s_tick;
    if (tick < NIMG - 16) return;

    const int n = tick - (NIMG - 16);
    if (t == 0) {
        while (atomicAdd(&g_cnt, 0) < NIMG) __nanosleep(64);
        __threadfence();
    }
    __syncthreads();

    if (t < 120) {
        int fv = t / 6, d = t % 6;
        r_feat[fv][d] = g_feat[(n * 20 + fv) * 6 + d];
        r_ps[fv][d]   = pos[(n * 20 + fv) * 6 + d];
    }
    __syncthreads();

    if (t < 20) {
        float a = 0.0f, bb = 0.0f;
#pragma unroll
        for (int k = 0; k < 6; k++) {
            a  += r_feat[t][k] * wfc_w[k]      + r_ps[t][k] * wfc_w[6 + k];
            bb += r_feat[t][k] * wfc_w[12 + k] + r_ps[t][k] * wfc_w[18 + k];
        }
        r_asrc[t] = a;
        r_btgt[t] = bb;
    }
    if (t < 120) {
        int fv = t / 6, d = t % 6;
        float s = fm_b[d];
#pragma unroll
        for (int k = 0; k < 6; k++) s += r_ps[fv][k] * fm_w[k * 6 + d];
        r_pm[fv][d] = s;
    }
    __syncthreads();

    if (t < 120) {
        int fv = t / 6, d = t % 6;
        int f = fv / 4, tv = fv % 4;
        float bias = wfc_b[0];
        float agg = 0.0f;
#pragma unroll
        for (int s = 0; s < 4; s++) {
            float z  = r_asrc[f * 4 + s] + r_btgt[f * 4 + tv] + bias;
            float lk = 1.0f / (1.0f + expf(-z));
            float m  = lk + attmap[((n * 5 + f) * 4 + s) * 4 + tv];
            agg += m * r_pm[f * 4 + s][d];
        }
        if (f > 0) {
            float lm = lm_b[d];
#pragma unroll
            for (int k = 0; k < 6; k++)
                lm += r_ps[(f - 1) * 4 + tv][k] * lm_w[k * 6 + d];
            agg += lm;
        }
        r_inp[fv * 12 + d]     = r_feat[fv][d];
        r_inp[fv * 12 + 6 + d] = agg;
    }
    __syncthreads();

    if (t < 240) {
        int half = t / 120, j = t - half * 120;
        int i0 = half * 120;
        float s = 0.0f;
#pragma unroll 12
        for (int i = 0; i < 120; i++)
            s += r_inp[i0 + i] * __ldg(fc1_w + (i0 + i) * 120 + j);
        r_part[t] = s;
    }
    __syncthreads();
    if (t < 120) r_r1[t] = fmaxf(r_part[t] + r_part[120 + t] + __ldg(fc1_b + t), 0.0f);
    __syncthreads();

    if (t < 120) {
        int half = t / 60, j = t - half * 60;
        int i0 = half * 60;
        float s = 0.0f;
#pragma unroll 12
        for (int i = 0; i < 60; i++)
            s += r_r1[i0 + i] * __ldg(fc2_w + (i0 + i) * 60 + j);
        r_part[t] = s;
    }
    __syncthreads();
    if (t < 60) r_r2[t] = fmaxf(r_part[t] + r_part[60 + t] + __ldg(fc2_b + t), 0.0f);
    __syncthreads();

    if (t < 6) {
        float s = __ldg(fc3_b + t);
#pragma unroll
        for (int i = 0; i < 60; i++) s += r_r2[i] * __ldg(fc3_w + i * 6 + t);
        out[n * 6 + t] = s;
    }
    __syncthreads();

    if (t == 0) {
        int r = atomicAdd(&g_done, 1);
        if (r == 15) {
            g_cnt = 0;
            __threadfence();
            g_done = 0;
        }
    }
}

// ---------------------------------------------------------------------------
extern "C" void kernel_launch(void* const* d_in, const int* in_sizes, int n_in,
                              void* d_out, int out_size)
{
    const float* nodes   = (const float*)d_in[0];
    const float* pos     = (const float*)d_in[1];
    const float* attmap  = (const float*)d_in[2];
    const float* conv1_w = (const float*)d_in[4];
    const float* conv1_b = (const float*)d_in[5];
    const float* conv2_w = (const float*)d_in[6];
    const float* conv2_b = (const float*)d_in[7];
    const float* lin_w   = (const float*)d_in[8];
    const float* lin_b   = (const float*)d_in[9];
    const float* wfc_w   = (const float*)d_in[10];
    const float* wfc_b   = (const float*)d_in[11];
    const float* fm_w    = (const float*)d_in[12];
    const float* fm_b    = (const float*)d_in[13];
    const float* lm_w    = (const float*)d_in[14];
    const float* lm_b    = (const float*)d_in[15];
    const float* fc1_w   = (const float*)d_in[16];
    const float* fc1_b   = (const float*)d_in[17];
    const float* fc2_w   = (const float*)d_in[18];
    const float* fc2_b   = (const float*)d_in[19];
    const float* fc3_w   = (const float*)d_in[20];
    const float* fc3_b   = (const float*)d_in[21];
    float* out = (float*)d_out;

    conv1_pool_kernel<<<NBLK1, 256>>>(nodes, conv1_w, conv1_b);
    epilogue_kernel<<<NIMG, 256>>>(pos, attmap, conv2_w, conv2_b,
                                   lin_w, lin_b, wfc_w, wfc_b, fm_w, fm_b,
                                   lm_w, lm_b, fc1_w, fc1_b, fc2_w, fc2_b,
                                   fc3_w, fc3_b, out);
}